// round 1
// baseline (speedup 1.0000x reference)
#include <cuda_runtime.h>

#define N_NODES 200000
#define HIDDIM  256
#define HEADS   8
#define HD      32
#define NC      1000

// ---------------- device scratch (static allocation only) ----------------
__device__ float g_QK[HIDDIM * HEADS];     // [j][h]  (scale folded in)
__device__ float g_bq[HEADS];              // bk contribution to scores
__device__ int   g_counts[NC];
__device__ int   g_offsets[NC + 1];
__device__ int   g_cursor[NC];
__device__ int   g_sorted[N_NODES];
__device__ float g_scores[N_NODES * HEADS];
__device__ float g_T[NC * HEADS * HIDDIM]; // unnormalized e-weighted sums
__device__ float g_z[NC * HEADS];          // softmax denominators
__device__ float g_pooled[NC * HIDDIM];
__device__ float g_outc[NC * HIDDIM];

// ---------------- prep: QK = scale * Wk^T q  per head; zero counts ----------------
__global__ void k_prep(const float* __restrict__ Wk, const float* __restrict__ bk,
                       const float* __restrict__ pq) {
    const float scale = 0.1767766952966369f;  // 32^-0.5
    int h = blockIdx.x;        // 0..7
    int j = threadIdx.x;       // 0..255
    float s = 0.f;
    #pragma unroll 8
    for (int d = 0; d < HD; d++)
        s += Wk[(h * HD + d) * HIDDIM + j] * pq[h * HD + d];
    g_QK[j * HEADS + h] = s * scale;
    if (j == 0) {
        float b = 0.f;
        for (int d = 0; d < HD; d++) b += bk[h * HD + d] * pq[h * HD + d];
        g_bq[h] = b * scale;
    }
    if (h == 0)
        for (int i = j; i < NC; i += blockDim.x) g_counts[i] = 0;
}

// ---------------- scores[n,h] = x[n]·QK[:,h] + bq[h] ----------------
// one warp per row, 8 rows per block
__global__ void k_scores(const float* __restrict__ x) {
    __shared__ float QKs[HIDDIM * 9];  // padded stride 9 -> conflict-free
    __shared__ float bqs[8];
    int tid = threadIdx.x;
    for (int i = tid; i < HIDDIM * HEADS; i += 256) {
        int j = i >> 3, h = i & 7;
        QKs[j * 9 + h] = g_QK[i];
    }
    if (tid < 8) bqs[tid] = g_bq[tid];
    __syncthreads();

    int warp = tid >> 5, lane = tid & 31;
    int n = blockIdx.x * 8 + warp;
    const float* xr = x + (size_t)n * HIDDIM;

    float s[8];
    #pragma unroll
    for (int h = 0; h < 8; h++) s[h] = 0.f;

    #pragma unroll
    for (int k = 0; k < 8; k++) {
        int j = lane + 32 * k;
        float xv = xr[j];
        #pragma unroll
        for (int h = 0; h < 8; h++) s[h] += xv * QKs[j * 9 + h];
    }
    #pragma unroll
    for (int off = 16; off; off >>= 1) {
        #pragma unroll
        for (int h = 0; h < 8; h++)
            s[h] += __shfl_xor_sync(0xffffffffu, s[h], off);
    }
    if (lane == 0) {
        float4 a = make_float4(s[0] + bqs[0], s[1] + bqs[1], s[2] + bqs[2], s[3] + bqs[3]);
        float4 b = make_float4(s[4] + bqs[4], s[5] + bqs[5], s[6] + bqs[6], s[7] + bqs[7]);
        float4* sp = (float4*)(g_scores + (size_t)n * 8);
        sp[0] = a; sp[1] = b;
    }
}

// ---------------- histogram of cluster sizes ----------------
__global__ void k_hist(const int* __restrict__ ca) {
    __shared__ int sh[NC];
    for (int i = threadIdx.x; i < NC; i += blockDim.x) sh[i] = 0;
    __syncthreads();
    for (int n = blockIdx.x * blockDim.x + threadIdx.x; n < N_NODES;
         n += gridDim.x * blockDim.x)
        atomicAdd(&sh[ca[n]], 1);
    __syncthreads();
    for (int i = threadIdx.x; i < NC; i += blockDim.x) {
        int v = sh[i];
        if (v) atomicAdd(&g_counts[i], v);
    }
}

// ---------------- exclusive prefix sum over counts ----------------
__global__ void k_scan() {
    __shared__ int buf[1024];
    int t = threadIdx.x;
    int v = (t < NC) ? g_counts[t] : 0;
    buf[t] = v;
    __syncthreads();
    for (int off = 1; off < 1024; off <<= 1) {
        int add = (t >= off) ? buf[t - off] : 0;
        __syncthreads();
        buf[t] += add;
        __syncthreads();
    }
    if (t < NC) {
        int excl = buf[t] - v;
        g_offsets[t] = excl;
        g_cursor[t]  = excl;
    }
    if (t == 0) g_offsets[NC] = N_NODES;
}

// ---------------- scatter node ids grouped by cluster ----------------
__global__ void k_scatter(const int* __restrict__ ca) {
    for (int n = blockIdx.x * blockDim.x + threadIdx.x; n < N_NODES;
         n += gridDim.x * blockDim.x) {
        int c = ca[n];
        int p = atomicAdd(&g_cursor[c], 1);
        g_sorted[p] = n;
    }
}

// ---------------- main: per-cluster T[h][j] = sum_n e[n,h] x[n,j], z[h] ----------------
__global__ void k_main(const float* __restrict__ x) {
    __shared__ float xs[32][HIDDIM];   // 32 KB tile of gathered x rows
    __shared__ float es[32][8];
    __shared__ int   sid[32];
    __shared__ float zs[256];

    int c = blockIdx.x, tid = threadIdx.x;
    int base = g_offsets[c];
    int cnt  = g_offsets[c + 1] - base;

    float T[8];
    #pragma unroll
    for (int h = 0; h < 8; h++) T[h] = 0.f;
    float zpart = 0.f;
    int en = tid >> 3, eh = tid & 7;

    for (int s0 = 0; s0 < cnt; s0 += 32) {
        int m = min(32, cnt - s0);
        if (tid < m) sid[tid] = g_sorted[base + s0 + tid];
        __syncthreads();
        // stage x rows (coalesced float4 per row)
        for (int i = tid; i < m * 64; i += 256) {
            int r = i >> 6, q = i & 63;
            ((float4*)xs[r])[q] = ((const float4*)x)[(size_t)sid[r] * 64 + q];
        }
        // exp of gathered scores (no max-subtraction: mathematically identical)
        if (en < m) {
            float e = __expf(g_scores[(size_t)sid[en] * 8 + eh]);
            es[en][eh] = e;
            zpart += e;
        }
        __syncthreads();
        // accumulate T: thread owns column j = tid
        for (int r = 0; r < m; r++) {
            float xv = xs[r][tid];
            float4 e0 = *(const float4*)&es[r][0];
            float4 e1 = *(const float4*)&es[r][4];
            T[0] += e0.x * xv; T[1] += e0.y * xv; T[2] += e0.z * xv; T[3] += e0.w * xv;
            T[4] += e1.x * xv; T[5] += e1.y * xv; T[6] += e1.z * xv; T[7] += e1.w * xv;
        }
        __syncthreads();
    }
    #pragma unroll
    for (int h = 0; h < 8; h++)
        g_T[((size_t)c * 8 + h) * HIDDIM + tid] = T[h];
    zs[tid] = zpart;
    __syncthreads();
    if (tid < 8) {
        float z = 0.f;
        for (int k = 0; k < 32; k++) z += zs[tid + 8 * k];
        g_z[c * 8 + tid] = z;
    }
}

// ---------------- pooled[c,hd] = (sum_j T'[c,h,j] Wv[hd,j] + bv[hd]) / cnt ----------------
// block handles 8 clusters x all 256 hd; K tiled by 32
__global__ void k_pooled(const float* __restrict__ Wv, const float* __restrict__ bv) {
    __shared__ float Ws[256 * 33];
    __shared__ float Ts[8][8][33];
    __shared__ float sinvz[8][8];
    __shared__ float sinvc[8];
    int tid = threadIdx.x;
    int c0 = blockIdx.x * 8;

    if (tid < 64) {
        int cc = tid >> 3, hh = tid & 7;
        float z = g_z[(c0 + cc) * 8 + hh];
        sinvz[cc][hh] = (z > 0.f) ? 1.f / z : 0.f;
    }
    if (tid < 8) {
        int cnt = g_offsets[c0 + tid + 1] - g_offsets[c0 + tid];
        sinvc[tid] = (cnt > 0) ? 1.f / (float)cnt : 0.f;
    }

    float acc[8];
    #pragma unroll
    for (int cc = 0; cc < 8; cc++) acc[cc] = 0.f;
    int h = tid >> 5;

    for (int kt = 0; kt < HIDDIM; kt += 32) {
        __syncthreads();
        for (int i = tid; i < 8192; i += 256) {
            int hd = i >> 5, kk = i & 31;
            Ws[hd * 33 + kk] = Wv[hd * HIDDIM + kt + kk];
        }
        for (int i = tid; i < 2048; i += 256) {
            int cc = i >> 8, hh = (i >> 5) & 7, kk = i & 31;
            Ts[cc][hh][kk] =
                g_T[((size_t)(c0 + cc) * 8 + hh) * HIDDIM + kt + kk] * sinvz[cc][hh];
        }
        __syncthreads();
        for (int kk = 0; kk < 32; kk++) {
            float w = Ws[tid * 33 + kk];
            #pragma unroll
            for (int cc = 0; cc < 8; cc++) acc[cc] += Ts[cc][h][kk] * w;
        }
    }
    float b = bv[tid];
    #pragma unroll
    for (int cc = 0; cc < 8; cc++)
        g_pooled[(size_t)(c0 + cc) * HIDDIM + tid] = (acc[cc] + b) * sinvc[cc];
}

// ---------------- out_c = pooled @ Wo^T + bo ----------------
__global__ void k_outc(const float* __restrict__ Wo, const float* __restrict__ bo) {
    __shared__ float Ws[256 * 33];
    __shared__ float Ps[8][33];
    int tid = threadIdx.x;
    int c0 = blockIdx.x * 8;

    float acc[8];
    #pragma unroll
    for (int cc = 0; cc < 8; cc++) acc[cc] = 0.f;

    for (int kt = 0; kt < HIDDIM; kt += 32) {
        __syncthreads();
        for (int i = tid; i < 8192; i += 256) {
            int hd = i >> 5, kk = i & 31;
            Ws[hd * 33 + kk] = Wo[hd * HIDDIM + kt + kk];
        }
        {
            int cc = tid >> 5, kk = tid & 31;
            Ps[cc][kk] = g_pooled[(size_t)(c0 + cc) * HIDDIM + kt + kk];
        }
        __syncthreads();
        for (int kk = 0; kk < 32; kk++) {
            float w = Ws[tid * 33 + kk];
            #pragma unroll
            for (int cc = 0; cc < 8; cc++) acc[cc] += Ps[cc][kk] * w;
        }
    }
    float b = bo[tid];
    #pragma unroll
    for (int cc = 0; cc < 8; cc++)
        g_outc[(size_t)(c0 + cc) * HIDDIM + tid] = acc[cc] + b;
}

// ---------------- out[n,:] = out_c[seg[n],:] ----------------
__global__ void k_bcast(const int* __restrict__ ca, float* __restrict__ out) {
    int r = blockIdx.x * 4 + (threadIdx.x >> 6);
    int q = threadIdx.x & 63;
    int c = ca[r];
    ((float4*)out)[(size_t)r * 64 + q] = ((const float4*)g_outc)[(size_t)c * 64 + q];
}

// ---------------- launch ----------------
extern "C" void kernel_launch(void* const* d_in, const int* in_sizes, int n_in,
                              void* d_out, int out_size) {
    const float* x  = (const float*)d_in[0];
    const int*   ca = (const int*)d_in[1];
    // d_in[2] = batch (unused)
    const float* Wk = (const float*)d_in[3];
    const float* bk = (const float*)d_in[4];
    const float* Wv = (const float*)d_in[5];
    const float* bv = (const float*)d_in[6];
    const float* Wo = (const float*)d_in[7];
    const float* bo = (const float*)d_in[8];
    const float* pq = (const float*)d_in[9];
    float* out = (float*)d_out;

    k_prep   <<<8, 256>>>(Wk, bk, pq);
    k_scores <<<N_NODES / 8, 256>>>(x);
    k_hist   <<<296, 256>>>(ca);
    k_scan   <<<1, 1024>>>();
    k_scatter<<<296, 256>>>(ca);
    k_main   <<<NC, 256>>>(x);
    k_pooled <<<NC / 8, 256>>>(Wv, bv);
    k_outc   <<<NC / 8, 256>>>(Wo, bo);
    k_bcast  <<<N_NODES / 4, 256>>>(ca, out);
}

// round 3
// speedup vs baseline: 1.3040x; 1.3040x over previous
#include <cuda_runtime.h>

#define N_NODES 200000
#define HIDDIM  256
#define HEADS   8
#define HD      32
#define NC      1000
#define TR      32   // rows per tile in k_main

// ---------------- device scratch ----------------
__device__ float g_QK[HIDDIM * HEADS];     // layout [hpair][j] float2 pairs, scale folded in
__device__ float g_bq[HEADS];
__device__ int   g_counts[NC];
__device__ int   g_offsets[NC + 1];
__device__ int   g_cursor[NC];
__device__ int   g_sorted[N_NODES];
__device__ float g_T[NC * HEADS * HIDDIM];
__device__ float g_z[NC * HEADS];
__device__ float g_pooled[NC * HIDDIM];
__device__ float g_outc[NC * HIDDIM];

// ---------------- helpers ----------------
__device__ __forceinline__ unsigned su32(const void* p) {
    return (unsigned)__cvta_generic_to_shared(p);
}
__device__ __forceinline__ void cpa16(void* dst, const void* src) {
    asm volatile("cp.async.cg.shared.global [%0], [%1], 16;"
                 :: "r"(su32(dst)), "l"(src));
}
__device__ __forceinline__ void cpa_commit() {
    asm volatile("cp.async.commit_group;");
}
template <int NN> __device__ __forceinline__ void cpa_wait() {
    asm volatile("cp.async.wait_group %0;" :: "n"(NN));
}
// packed f32x2 fma (sm_100+)
__device__ __forceinline__ float2 ffma2(float2 a, float2 b, float2 c) {
    float2 d;
    asm("{\n\t"
        ".reg .b64 A,B,C,D;\n\t"
        "mov.b64 A,{%2,%3};\n\t"
        "mov.b64 B,{%4,%5};\n\t"
        "mov.b64 C,{%6,%7};\n\t"
        "fma.rn.f32x2 D,A,B,C;\n\t"
        "mov.b64 {%0,%1},D;\n\t"
        "}"
        : "=f"(d.x), "=f"(d.y)
        : "f"(a.x), "f"(a.y), "f"(b.x), "f"(b.y), "f"(c.x), "f"(c.y));
    return d;
}

// ---------------- prep: QK[hp][j] pairs = scale * Wk^T q; zero counts ----------------
__global__ void k_prep(const float* __restrict__ Wk, const float* __restrict__ bk,
                       const float* __restrict__ pq) {
    const float scale = 0.1767766952966369f;  // 32^-0.5
    int h = blockIdx.x;        // 0..7
    int j = threadIdx.x;       // 0..255
    float s = 0.f;
    #pragma unroll 8
    for (int d = 0; d < HD; d++)
        s += Wk[(h * HD + d) * HIDDIM + j] * pq[h * HD + d];
    // pair layout: element = ((h>>1)*256 + j)*2 + (h&1)
    g_QK[(((h >> 1) * HIDDIM) + j) * 2 + (h & 1)] = s * scale;
    if (j == 0) {
        float b = 0.f;
        for (int d = 0; d < HD; d++) b += bk[h * HD + d] * pq[h * HD + d];
        g_bq[h] = b * scale;
    }
    if (h == 0)
        for (int i = j; i < NC; i += blockDim.x) g_counts[i] = 0;
}

// ---------------- histogram ----------------
__global__ void k_hist(const int* __restrict__ ca) {
    __shared__ int sh[NC];
    for (int i = threadIdx.x; i < NC; i += blockDim.x) sh[i] = 0;
    __syncthreads();
    for (int n = blockIdx.x * blockDim.x + threadIdx.x; n < N_NODES;
         n += gridDim.x * blockDim.x)
        atomicAdd(&sh[ca[n]], 1);
    __syncthreads();
    for (int i = threadIdx.x; i < NC; i += blockDim.x) {
        int v = sh[i];
        if (v) atomicAdd(&g_counts[i], v);
    }
}

// ---------------- exclusive scan ----------------
__global__ void k_scan() {
    __shared__ int buf[1024];
    int t = threadIdx.x;
    int v = (t < NC) ? g_counts[t] : 0;
    buf[t] = v;
    __syncthreads();
    for (int off = 1; off < 1024; off <<= 1) {
        int add = (t >= off) ? buf[t - off] : 0;
        __syncthreads();
        buf[t] += add;
        __syncthreads();
    }
    if (t < NC) {
        int excl = buf[t] - v;
        g_offsets[t] = excl;
        g_cursor[t]  = excl;
    }
    if (t == 0) g_offsets[NC] = N_NODES;
}

// ---------------- scatter ----------------
__global__ void k_scatter(const int* __restrict__ ca) {
    for (int n = blockIdx.x * blockDim.x + threadIdx.x; n < N_NODES;
         n += gridDim.x * blockDim.x) {
        int c = ca[n];
        int p = atomicAdd(&g_cursor[c], 1);
        g_sorted[p] = n;
    }
}

// ---------------- main (fused scores + softmax-exp + weighted accumulation) ----------------
// dyn smem layout (bytes):
//   xs   : 2 * TR * 256 floats  = 65536
//   QKs  : 4 * 256 float2       =  8192
//   es2  : TR * 4 float2        =  1024   (TR rows x 8 heads)
//   zsh  : 64 floats            =   256
//   bqs  : 8 floats + pad       =    64
#define SM_XS   0
#define SM_QK   65536
#define SM_ES   (SM_QK + 8192)
#define SM_ZSH  (SM_ES + 1024)
#define SM_BQ   (SM_ZSH + 256)
#define SMEM_MAIN (SM_BQ + 64)

__global__ void __launch_bounds__(256) k_main(const float* __restrict__ x) {
    extern __shared__ char smem[];
    float*  xs  = (float*)(smem + SM_XS);          // [2][TR][256]
    float2* QKs = (float2*)(smem + SM_QK);         // [4][256]
    float2* es2 = (float2*)(smem + SM_ES);         // [TR][4]
    float*  zsh = (float*)(smem + SM_ZSH);         // [8][8]
    float*  bqs = (float*)(smem + SM_BQ);

    int c = blockIdx.x, tid = threadIdx.x;
    int warp = tid >> 5, lane = tid & 31;
    int base = g_offsets[c];
    int cnt  = g_offsets[c + 1] - base;
    int ntiles = (cnt + TR - 1) / TR;

    for (int i = tid; i < HIDDIM * 4; i += 256)
        QKs[i] = ((const float2*)g_QK)[i];
    if (tid < 8) bqs[tid] = g_bq[tid];
    __syncthreads();

    float2 T01 = make_float2(0.f, 0.f), T23 = T01, T45 = T01, T67 = T01;
    float zacc = 0.f;  // per-warp, valid for lane<8 (head = lane)

    // staging: thread handles row r = tid>>3, chunk col q = (tid&7) + 8k
    int my_r = tid >> 3;
    int my_q = tid & 7;

    // prologue: issue tile 0
    if (ntiles > 0) {
        int m0 = min(TR, cnt);
        if (my_r < m0) {
            int row = __ldg(&g_sorted[base + my_r]);
            const float4* src = ((const float4*)x) + (size_t)row * 64 + my_q;
            float4* dst = ((float4*)(xs + (size_t)my_r * HIDDIM)) + my_q;
            #pragma unroll
            for (int kk = 0; kk < 8; kk++)
                cpa16(dst + 8 * kk, src + 8 * kk);
        }
    }
    cpa_commit();

    for (int t = 0; t < ntiles; t++) {
        int b = t & 1;
        int m = min(TR, cnt - t * TR);
        float* xsb = xs + (size_t)b * TR * HIDDIM;

        if (t + 1 < ntiles) {
            int m2 = min(TR, cnt - (t + 1) * TR);
            float* xsn = xs + (size_t)(b ^ 1) * TR * HIDDIM;
            if (my_r < m2) {
                int row = __ldg(&g_sorted[base + (t + 1) * TR + my_r]);
                const float4* src = ((const float4*)x) + (size_t)row * 64 + my_q;
                float4* dst = ((float4*)(xsn + (size_t)my_r * HIDDIM)) + my_q;
                #pragma unroll
                for (int kk = 0; kk < 8; kk++)
                    cpa16(dst + 8 * kk, src + 8 * kk);
            }
            cpa_commit();
            cpa_wait<1>();
        } else {
            cpa_wait<0>();
        }
        __syncthreads();

        // ---- scores: warp handles rows 4*warp .. 4*warp+3 ----
        {
            float2 s[4][4];
            #pragma unroll
            for (int rr = 0; rr < 4; rr++)
                #pragma unroll
                for (int p = 0; p < 4; p++) s[rr][p] = make_float2(0.f, 0.f);

            #pragma unroll
            for (int k = 0; k < 8; k++) {
                int j = lane + 32 * k;
                float2 q0 = QKs[0 * HIDDIM + j];
                float2 q1 = QKs[1 * HIDDIM + j];
                float2 q2 = QKs[2 * HIDDIM + j];
                float2 q3 = QKs[3 * HIDDIM + j];
                #pragma unroll
                for (int rr = 0; rr < 4; rr++) {
                    float xv = xsb[(warp * 4 + rr) * HIDDIM + j];
                    float2 xx = make_float2(xv, xv);
                    s[rr][0] = ffma2(xx, q0, s[rr][0]);
                    s[rr][1] = ffma2(xx, q1, s[rr][1]);
                    s[rr][2] = ffma2(xx, q2, s[rr][2]);
                    s[rr][3] = ffma2(xx, q3, s[rr][3]);
                }
            }
            #pragma unroll
            for (int rr = 0; rr < 4; rr++) {
                int r = warp * 4 + rr;
                float v[8] = {s[rr][0].x, s[rr][0].y, s[rr][1].x, s[rr][1].y,
                              s[rr][2].x, s[rr][2].y, s[rr][3].x, s[rr][3].y};
                #pragma unroll
                for (int off = 16; off; off >>= 1)
                    #pragma unroll
                    for (int h = 0; h < 8; h++)
                        v[h] += __shfl_xor_sync(0xffffffffu, v[h], off);
                if (lane < 8 && r < m) {
                    float sv = v[0];
                    #pragma unroll
                    for (int h = 1; h < 8; h++) sv = (lane == h) ? v[h] : sv;
                    float e = __expf(sv + bqs[lane]);
                    ((float*)(es2 + r * 4))[lane] = e;
                    zacc += e;
                }
            }
        }
        __syncthreads();

        // ---- accumulate T: thread owns column j = tid ----
        for (int r = 0; r < m; r++) {
            float xv = xsb[r * HIDDIM + tid];
            float2 xx = make_float2(xv, xv);
            const float2* ep = es2 + r * 4;
            T01 = ffma2(ep[0], xx, T01);
            T23 = ffma2(ep[1], xx, T23);
            T45 = ffma2(ep[2], xx, T45);
            T67 = ffma2(ep[3], xx, T67);
        }
        __syncthreads();
    }

    float* Tp = g_T + (size_t)c * 8 * HIDDIM;
    Tp[0 * HIDDIM + tid] = T01.x;
    Tp[1 * HIDDIM + tid] = T01.y;
    Tp[2 * HIDDIM + tid] = T23.x;
    Tp[3 * HIDDIM + tid] = T23.y;
    Tp[4 * HIDDIM + tid] = T45.x;
    Tp[5 * HIDDIM + tid] = T45.y;
    Tp[6 * HIDDIM + tid] = T67.x;
    Tp[7 * HIDDIM + tid] = T67.y;

    if (lane < 8) zsh[warp * 8 + lane] = zacc;
    __syncthreads();
    if (tid < 8) {
        float z = 0.f;
        #pragma unroll
        for (int w = 0; w < 8; w++) z += zsh[w * 8 + tid];
        g_z[c * 8 + tid] = z;
    }
}

// ---------------- pooled[c,hd] = (sum_j T'[c,h,j] Wv[hd,j] + bv[hd]) / cnt ----------------
__global__ void k_pooled(const float* __restrict__ Wv, const float* __restrict__ bv) {
    __shared__ float Ws[256 * 33];
    __shared__ float Ts[8][8][33];
    __shared__ float sinvz[8][8];
    __shared__ float sinvc[8];
    int tid = threadIdx.x;
    int c0 = blockIdx.x * 8;

    if (tid < 64) {
        int cc = tid >> 3, hh = tid & 7;
        float z = g_z[(c0 + cc) * 8 + hh];
        sinvz[cc][hh] = (z > 0.f) ? 1.f / z : 0.f;
    }
    if (tid < 8) {
        int cnt = g_offsets[c0 + tid + 1] - g_offsets[c0 + tid];
        sinvc[tid] = (cnt > 0) ? 1.f / (float)cnt : 0.f;
    }

    float acc[8];
    #pragma unroll
    for (int cc = 0; cc < 8; cc++) acc[cc] = 0.f;
    int h = tid >> 5;

    for (int kt = 0; kt < HIDDIM; kt += 32) {
        __syncthreads();
        for (int i = tid; i < 8192; i += 256) {
            int hd = i >> 5, kk = i & 31;
            Ws[hd * 33 + kk] = Wv[hd * HIDDIM + kt + kk];
        }
        for (int i = tid; i < 2048; i += 256) {
            int cc = i >> 8, hh = (i >> 5) & 7, kk = i & 31;
            Ts[cc][hh][kk] =
                g_T[((size_t)(c0 + cc) * 8 + hh) * HIDDIM + kt + kk] * sinvz[cc][hh];
        }
        __syncthreads();
        for (int kk = 0; kk < 32; kk++) {
            float w = Ws[tid * 33 + kk];
            #pragma unroll
            for (int cc = 0; cc < 8; cc++) acc[cc] += Ts[cc][h][kk] * w;
        }
    }
    float b = bv[tid];
    #pragma unroll
    for (int cc = 0; cc < 8; cc++)
        g_pooled[(size_t)(c0 + cc) * HIDDIM + tid] = (acc[cc] + b) * sinvc[cc];
}

// ---------------- out_c = pooled @ Wo^T + bo ----------------
__global__ void k_outc(const float* __restrict__ Wo, const float* __restrict__ bo) {
    __shared__ float Ws[256 * 33];
    __shared__ float Ps[8][33];
    int tid = threadIdx.x;
    int c0 = blockIdx.x * 8;

    float acc[8];
    #pragma unroll
    for (int cc = 0; cc < 8; cc++) acc[cc] = 0.f;

    for (int kt = 0; kt < HIDDIM; kt += 32) {
        __syncthreads();
        for (int i = tid; i < 8192; i += 256) {
            int hd = i >> 5, kk = i & 31;
            Ws[hd * 33 + kk] = Wo[hd * HIDDIM + kt + kk];
        }
        {
            int cc = tid >> 5, kk = tid & 31;
            Ps[cc][kk] = g_pooled[(size_t)(c0 + cc) * HIDDIM + kt + kk];
        }
        __syncthreads();
        for (int kk = 0; kk < 32; kk++) {
            float w = Ws[tid * 33 + kk];
            #pragma unroll
            for (int cc = 0; cc < 8; cc++) acc[cc] += Ps[cc][kk] * w;
        }
    }
    float b = bo[tid];
    #pragma unroll
    for (int cc = 0; cc < 8; cc++)
        g_outc[(size_t)(c0 + cc) * HIDDIM + tid] = acc[cc] + b;
}

// ---------------- out[n,:] = out_c[seg[n],:] ----------------
__global__ void k_bcast(const int* __restrict__ ca, float* __restrict__ out) {
    int r = blockIdx.x * 4 + (threadIdx.x >> 6);
    int q = threadIdx.x & 63;
    int c = __ldg(&ca[r]);
    ((float4*)out)[(size_t)r * 64 + q] = ((const float4*)g_outc)[(size_t)c * 64 + q];
}

// ---------------- launch ----------------
extern "C" void kernel_launch(void* const* d_in, const int* in_sizes, int n_in,
                              void* d_out, int out_size) {
    const float* x  = (const float*)d_in[0];
    const int*   ca = (const int*)d_in[1];
    // d_in[2] = batch (unused)
    const float* Wk = (const float*)d_in[3];
    const float* bk = (const float*)d_in[4];
    const float* Wv = (const float*)d_in[5];
    const float* bv = (const float*)d_in[6];
    const float* Wo = (const float*)d_in[7];
    const float* bo = (const float*)d_in[8];
    const float* pq = (const float*)d_in[9];
    float* out = (float*)d_out;

    cudaFuncSetAttribute(k_main, cudaFuncAttributeMaxDynamicSharedMemorySize,
                         SMEM_MAIN);

    k_prep   <<<8, 256>>>(Wk, bk, pq);
    k_hist   <<<296, 256>>>(ca);
    k_scan   <<<1, 1024>>>();
    k_scatter<<<296, 256>>>(ca);
    k_main   <<<NC, 256, SMEM_MAIN>>>(x);
    k_pooled <<<NC / 8, 256>>>(Wv, bv);
    k_outc   <<<NC / 8, 256>>>(Wo, bo);
    k_bcast  <<<N_NODES / 4, 256>>>(ca, out);
}

// round 4
// speedup vs baseline: 1.5907x; 1.2199x over previous
#include <cuda_runtime.h>

#define N_NODES 200000
#define HIDDIM  256
#define HEADS   8
#define HD      32
#define NC      1000
#define TR      32     // rows per tile in k_main
#define NB      64     // blocks in sort pipeline
#define CHUNK   (N_NODES / NB)   // 3125, exact

// ---------------- device scratch ----------------
__device__ float g_QK[HIDDIM * HEADS];       // [hpair][j] float2 pairs, scale folded in
__device__ float g_bq[HEADS];
__device__ int   g_bh[NB * NC];              // per-block cluster histograms -> bases
__device__ int   g_offsets[NC + 1];
__device__ int   g_sorted[N_NODES];
__device__ float g_T[2 * NC * HEADS * HIDDIM];  // per half-cluster partial sums
__device__ float g_z[2 * NC * HEADS];

// ---------------- helpers ----------------
__device__ __forceinline__ unsigned su32(const void* p) {
    return (unsigned)__cvta_generic_to_shared(p);
}
__device__ __forceinline__ void cpa16(void* dst, const void* src) {
    asm volatile("cp.async.cg.shared.global [%0], [%1], 16;"
                 :: "r"(su32(dst)), "l"(src));
}
__device__ __forceinline__ void cpa_commit() {
    asm volatile("cp.async.commit_group;");
}
template <int NN> __device__ __forceinline__ void cpa_wait() {
    asm volatile("cp.async.wait_group %0;" :: "n"(NN));
}
__device__ __forceinline__ float2 ffma2(float2 a, float2 b, float2 c) {
    float2 d;
    asm("{\n\t"
        ".reg .b64 A,B,C,D;\n\t"
        "mov.b64 A,{%2,%3};\n\t"
        "mov.b64 B,{%4,%5};\n\t"
        "mov.b64 C,{%6,%7};\n\t"
        "fma.rn.f32x2 D,A,B,C;\n\t"
        "mov.b64 {%0,%1},D;\n\t"
        "}"
        : "=f"(d.x), "=f"(d.y)
        : "f"(a.x), "f"(a.y), "f"(b.x), "f"(b.y), "f"(c.x), "f"(c.y));
    return d;
}

// ---------------- prep: QK[hp][j] pairs = scale * Wk^T q ----------------
__global__ void k_prep(const float* __restrict__ Wk, const float* __restrict__ bk,
                       const float* __restrict__ pq) {
    const float scale = 0.1767766952966369f;  // 32^-0.5
    int h = blockIdx.x;        // 0..7
    int j = threadIdx.x;       // 0..255
    float s = 0.f;
    #pragma unroll 8
    for (int d = 0; d < HD; d++)
        s += Wk[(h * HD + d) * HIDDIM + j] * pq[h * HD + d];
    g_QK[(((h >> 1) * HIDDIM) + j) * 2 + (h & 1)] = s * scale;
    if (j == 0) {
        float b = 0.f;
        for (int d = 0; d < HD; d++) b += bk[h * HD + d] * pq[h * HD + d];
        g_bq[h] = b * scale;
    }
}

// ---------------- per-block histogram (no global atomics) ----------------
__global__ void k_hist2(const int* __restrict__ ca) {
    __shared__ int sh[NC];
    int b = blockIdx.x, tid = threadIdx.x;
    for (int i = tid; i < NC; i += 256) sh[i] = 0;
    __syncthreads();
    int n0 = b * CHUNK;
    for (int i = tid; i < CHUNK; i += 256)
        atomicAdd(&sh[ca[n0 + i]], 1);
    __syncthreads();
    for (int i = tid; i < NC; i += 256) g_bh[b * NC + i] = sh[i];
}

// ---------------- scan: cluster offsets + per-block bases ----------------
__global__ void k_scan2() {
    __shared__ int buf[1024];
    int t = threadIdx.x;
    int total = 0;
    if (t < NC) {
        // local exclusive scan over blocks for cluster t
        int s = 0;
        for (int b = 0; b < NB; b++) {
            int v = g_bh[b * NC + t];
            g_bh[b * NC + t] = s;
            s += v;
        }
        total = s;
    }
    buf[t] = total;
    __syncthreads();
    for (int off = 1; off < 1024; off <<= 1) {
        int add = (t >= off) ? buf[t - off] : 0;
        __syncthreads();
        buf[t] += add;
        __syncthreads();
    }
    if (t < NC) {
        int excl = buf[t] - total;
        g_offsets[t] = excl;
        for (int b = 0; b < NB; b++) g_bh[b * NC + t] += excl;
    }
    if (t == 0) g_offsets[NC] = N_NODES;
}

// ---------------- scatter (shared-memory cursors only) ----------------
__global__ void k_scatter2(const int* __restrict__ ca) {
    __shared__ int cur[NC];
    int b = blockIdx.x, tid = threadIdx.x;
    for (int i = tid; i < NC; i += 256) cur[i] = g_bh[b * NC + i];
    __syncthreads();
    int n0 = b * CHUNK;
    for (int i = tid; i < CHUNK; i += 256) {
        int n = n0 + i;
        int c = ca[n];
        int p = atomicAdd(&cur[c], 1);
        g_sorted[p] = n;
    }
}

// ---------------- main (fused scores + exp + weighted accumulation, half-clusters) ---
// dyn smem (bytes): xs 2*TR*256*4=65536 | QKs 8192 | es2 1024 | zsh 256 | bqs 64
#define SM_XS   0
#define SM_QK   65536
#define SM_ES   (SM_QK + 8192)
#define SM_ZSH  (SM_ES + 1024)
#define SM_BQ   (SM_ZSH + 256)
#define SMEM_MAIN (SM_BQ + 64)

__global__ void __launch_bounds__(256) k_main(const float* __restrict__ x) {
    extern __shared__ char smem[];
    float*  xs  = (float*)(smem + SM_XS);          // [2][TR][256]
    float2* QKs = (float2*)(smem + SM_QK);         // [4][256]
    float2* es2 = (float2*)(smem + SM_ES);         // [TR][4]
    float*  zsh = (float*)(smem + SM_ZSH);         // [8][8]
    float*  bqs = (float*)(smem + SM_BQ);

    int tid = threadIdx.x;
    int warp = tid >> 5, lane = tid & 31;

    int cidx = blockIdx.x >> 1, half = blockIdx.x & 1;
    int cbase = g_offsets[cidx];
    int ccnt  = g_offsets[cidx + 1] - cbase;
    int hl    = (ccnt + 1) >> 1;
    int start = half * hl;
    int cnt   = min(hl, ccnt - start);
    if (cnt < 0) cnt = 0;
    int base  = cbase + start;
    int ntiles = (cnt + TR - 1) / TR;

    for (int i = tid; i < HIDDIM * 4; i += 256)
        QKs[i] = ((const float2*)g_QK)[i];
    if (tid < 8) bqs[tid] = g_bq[tid];
    __syncthreads();

    float2 T01 = make_float2(0.f, 0.f), T23 = T01, T45 = T01, T67 = T01;
    float zacc = 0.f;  // valid for lane<8 (head = lane)

    int my_r = tid >> 3;
    int my_q = tid & 7;

    if (ntiles > 0) {
        int m0 = min(TR, cnt);
        if (my_r < m0) {
            int row = __ldg(&g_sorted[base + my_r]);
            const float4* src = ((const float4*)x) + (size_t)row * 64 + my_q;
            float4* dst = ((float4*)(xs + (size_t)my_r * HIDDIM)) + my_q;
            #pragma unroll
            for (int kk = 0; kk < 8; kk++)
                cpa16(dst + 8 * kk, src + 8 * kk);
        }
    }
    cpa_commit();

    for (int t = 0; t < ntiles; t++) {
        int b = t & 1;
        int m = min(TR, cnt - t * TR);
        float* xsb = xs + (size_t)b * TR * HIDDIM;

        if (t + 1 < ntiles) {
            int m2 = min(TR, cnt - (t + 1) * TR);
            float* xsn = xs + (size_t)(b ^ 1) * TR * HIDDIM;
            if (my_r < m2) {
                int row = __ldg(&g_sorted[base + (t + 1) * TR + my_r]);
                const float4* src = ((const float4*)x) + (size_t)row * 64 + my_q;
                float4* dst = ((float4*)(xsn + (size_t)my_r * HIDDIM)) + my_q;
                #pragma unroll
                for (int kk = 0; kk < 8; kk++)
                    cpa16(dst + 8 * kk, src + 8 * kk);
            }
            cpa_commit();
            cpa_wait<1>();
        } else {
            cpa_wait<0>();
        }
        __syncthreads();

        // ---- scores: warp handles rows 4*warp .. 4*warp+3 ----
        {
            float2 s[4][4];
            #pragma unroll
            for (int rr = 0; rr < 4; rr++)
                #pragma unroll
                for (int p = 0; p < 4; p++) s[rr][p] = make_float2(0.f, 0.f);

            #pragma unroll
            for (int k = 0; k < 8; k++) {
                int j = lane + 32 * k;
                float2 q0 = QKs[0 * HIDDIM + j];
                float2 q1 = QKs[1 * HIDDIM + j];
                float2 q2 = QKs[2 * HIDDIM + j];
                float2 q3 = QKs[3 * HIDDIM + j];
                #pragma unroll
                for (int rr = 0; rr < 4; rr++) {
                    float xv = xsb[(warp * 4 + rr) * HIDDIM + j];
                    float2 xx = make_float2(xv, xv);
                    s[rr][0] = ffma2(xx, q0, s[rr][0]);
                    s[rr][1] = ffma2(xx, q1, s[rr][1]);
                    s[rr][2] = ffma2(xx, q2, s[rr][2]);
                    s[rr][3] = ffma2(xx, q3, s[rr][3]);
                }
            }
            #pragma unroll
            for (int rr = 0; rr < 4; rr++) {
                int r = warp * 4 + rr;
                float v[8] = {s[rr][0].x, s[rr][0].y, s[rr][1].x, s[rr][1].y,
                              s[rr][2].x, s[rr][2].y, s[rr][3].x, s[rr][3].y};
                #pragma unroll
                for (int off = 16; off; off >>= 1)
                    #pragma unroll
                    for (int h = 0; h < 8; h++)
                        v[h] += __shfl_xor_sync(0xffffffffu, v[h], off);
                if (lane < 8 && r < m) {
                    float sv = v[0];
                    #pragma unroll
                    for (int h = 1; h < 8; h++) sv = (lane == h) ? v[h] : sv;
                    float e = __expf(sv + bqs[lane]);
                    ((float*)(es2 + r * 4))[lane] = e;
                    zacc += e;
                }
            }
        }
        __syncthreads();

        // ---- accumulate T: thread owns column j = tid ----
        for (int r = 0; r < m; r++) {
            float xv = xsb[r * HIDDIM + tid];
            float2 xx = make_float2(xv, xv);
            float4 ea = ((const float4*)(es2 + r * 4))[0];
            float4 eb = ((const float4*)(es2 + r * 4))[1];
            T01 = ffma2(make_float2(ea.x, ea.y), xx, T01);
            T23 = ffma2(make_float2(ea.z, ea.w), xx, T23);
            T45 = ffma2(make_float2(eb.x, eb.y), xx, T45);
            T67 = ffma2(make_float2(eb.z, eb.w), xx, T67);
        }
        __syncthreads();
    }

    float* Tp = g_T + (size_t)blockIdx.x * 8 * HIDDIM;
    Tp[0 * HIDDIM + tid] = T01.x;
    Tp[1 * HIDDIM + tid] = T01.y;
    Tp[2 * HIDDIM + tid] = T23.x;
    Tp[3 * HIDDIM + tid] = T23.y;
    Tp[4 * HIDDIM + tid] = T45.x;
    Tp[5 * HIDDIM + tid] = T45.y;
    Tp[6 * HIDDIM + tid] = T67.x;
    Tp[7 * HIDDIM + tid] = T67.y;

    if (lane < 8) zsh[warp * 8 + lane] = zacc;
    __syncthreads();
    if (tid < 8) {
        float z = 0.f;
        #pragma unroll
        for (int w = 0; w < 8; w++) z += zsh[w * 8 + tid];
        g_z[blockIdx.x * 8 + tid] = z;
    }
}

// ---------------- fused: pooled (Wv) -> outc (Wo) -> scatter output ----------------
// block handles 8 clusters; static smem: Ws 33792B, TsPp 8448B, small arrays
__global__ void __launch_bounds__(256) k_fused(
    const float* __restrict__ Wv, const float* __restrict__ bv,
    const float* __restrict__ Wo, const float* __restrict__ bo,
    float* __restrict__ out) {
    __shared__ float Ws[256 * 33];
    __shared__ float TsPp[2112];     // Ts[8][8][33] in phase1, rows/Pp[8][256] later
    __shared__ float sinvz[64];
    __shared__ float sinvc[8];
    __shared__ int   sids[256];

    int tid = threadIdx.x;
    int c0 = blockIdx.x * 8;
    int h = tid >> 5;

    if (tid < 64) {
        int cc = tid >> 3, hh = tid & 7;
        float z = g_z[(c0 + cc) * 16 + hh] + g_z[(c0 + cc) * 16 + 8 + hh];
        sinvz[tid] = (z > 0.f) ? 1.f / z : 0.f;
    }
    if (tid < 8) {
        int cnt = g_offsets[c0 + tid + 1] - g_offsets[c0 + tid];
        sinvc[tid] = (cnt > 0) ? 1.f / (float)cnt : 0.f;
    }

    // ---- phase 1: pooled[c][hd] = (sum_j T'[c,h,j] Wv[hd,j] + bv[hd]) / cnt ----
    float acc[8];
    #pragma unroll
    for (int cc = 0; cc < 8; cc++) acc[cc] = 0.f;

    for (int kt = 0; kt < HIDDIM; kt += 32) {
        __syncthreads();
        for (int i = tid; i < 8192; i += 256) {
            int hd = i >> 5, kk = i & 31;
            Ws[hd * 33 + kk] = Wv[hd * HIDDIM + kt + kk];
        }
        for (int i = tid; i < 2048; i += 256) {
            int cc = i >> 8, hh = (i >> 5) & 7, kk = i & 31;
            size_t b0 = ((size_t)(c0 + cc) * 2) * 2048 + hh * 256 + kt + kk;
            TsPp[(cc * 8 + hh) * 33 + kk] =
                (g_T[b0] + g_T[b0 + 2048]) * sinvz[cc * 8 + hh];
        }
        __syncthreads();
        for (int kk = 0; kk < 32; kk++) {
            float w = Ws[tid * 33 + kk];
            #pragma unroll
            for (int cc = 0; cc < 8; cc++) acc[cc] += TsPp[(cc * 8 + h) * 33 + kk] * w;
        }
    }
    __syncthreads();
    {
        float bvv = bv[tid];
        #pragma unroll
        for (int cc = 0; cc < 8; cc++)
            TsPp[cc * 256 + tid] = (acc[cc] + bvv) * sinvc[cc];  // Pp[cc][hd]
    }
    __syncthreads();

    // ---- phase 2: outc[c][d] = sum_k pooled[c][k] * Wo[d][k] + bo[d] ----
    float acc2[8];
    #pragma unroll
    for (int cc = 0; cc < 8; cc++) acc2[cc] = 0.f;

    for (int kt = 0; kt < HIDDIM; kt += 32) {
        __syncthreads();
        for (int i = tid; i < 8192; i += 256) {
            int hd = i >> 5, kk = i & 31;
            Ws[hd * 33 + kk] = Wo[hd * HIDDIM + kt + kk];
        }
        __syncthreads();
        for (int kk = 0; kk < 32; kk++) {
            float w = Ws[tid * 33 + kk];
            #pragma unroll
            for (int cc = 0; cc < 8; cc++) acc2[cc] += TsPp[cc * 256 + kt + kk] * w;
        }
    }
    __syncthreads();
    {
        float bov = bo[tid];
        #pragma unroll
        for (int cc = 0; cc < 8; cc++)
            TsPp[cc * 256 + tid] = acc2[cc] + bov;   // out rows
    }
    __syncthreads();

    // ---- phase 3: out[n,:] = outrow[cc] for every member n of cluster ----
    int g = tid >> 6, l64 = tid & 63;
    for (int cc = 0; cc < 8; cc++) {
        int c = c0 + cc;
        int base = g_offsets[c];
        int cnt  = g_offsets[c + 1] - base;
        float4 ov = ((const float4*)(TsPp + cc * 256))[l64];
        for (int i0 = 0; i0 < cnt; i0 += 256) {
            int m = min(256, cnt - i0);
            __syncthreads();
            if (tid < m) sids[tid] = g_sorted[base + i0 + tid];
            __syncthreads();
            for (int k = 0; k < m; k += 4) {
                int idx = k + g;
                if (idx < m) {
                    size_t n = (size_t)sids[idx];
                    ((float4*)out)[n * 64 + l64] = ov;
                }
            }
        }
    }
}

// ---------------- launch ----------------
extern "C" void kernel_launch(void* const* d_in, const int* in_sizes, int n_in,
                              void* d_out, int out_size) {
    const float* x  = (const float*)d_in[0];
    const int*   ca = (const int*)d_in[1];
    // d_in[2] = batch (unused)
    const float* Wk = (const float*)d_in[3];
    const float* bk = (const float*)d_in[4];
    const float* Wv = (const float*)d_in[5];
    const float* bv = (const float*)d_in[6];
    const float* Wo = (const float*)d_in[7];
    const float* bo = (const float*)d_in[8];
    const float* pq = (const float*)d_in[9];
    float* out = (float*)d_out;

    cudaFuncSetAttribute(k_main, cudaFuncAttributeMaxDynamicSharedMemorySize,
                         SMEM_MAIN);

    k_prep    <<<8, 256>>>(Wk, bk, pq);
    k_hist2   <<<NB, 256>>>(ca);
    k_scan2   <<<1, 1024>>>();
    k_scatter2<<<NB, 256>>>(ca);
    k_main    <<<2 * NC, 256, SMEM_MAIN>>>(x);
    k_fused   <<<NC / 8, 256>>>(Wv, bv, Wo, bo, out);
}